// round 8
// baseline (speedup 1.0000x reference)
#include <cuda_runtime.h>
#include <cuda_bf16.h>
#include <cstdint>
#include <math.h>

namespace {
constexpr int TT = 4096;   // tokens (B*S)
constexpr int DD = 1024;   // model dim
constexpr int EE = 8;      // experts
constexpr int FF = 4096;   // ffn dim
}

// ---------------- device scratch (no runtime allocation allowed) -----------
__device__ int g_expert_id[TT];
__device__ int g_counts[EE];
__device__ int g_offsets[EE];
__device__ int g_cursor[EE];
__device__ int g_perm[TT];
__device__ __nv_bfloat16 g_h_hi[(size_t)TT * FF];   // 32 MB
__device__ __nv_bfloat16 g_h_lo[(size_t)TT * FF];   // 32 MB

// ---------------- helpers ---------------------------------------------------
__device__ __forceinline__ uint32_t smem_u32(const void* p) {
    uint32_t a;
    asm("{ .reg .u64 t; cvta.to.shared.u64 t, %1; cvt.u32.u64 %0, t; }" : "=r"(a) : "l"(p));
    return a;
}
// fp32 -> bf16 (hi, lo) split, packed as bf16x2 pairs
__device__ __forceinline__ void split2(float a, float b, uint32_t& hi, uint32_t& lo) {
    __nv_bfloat16 ha = __float2bfloat16(a);
    __nv_bfloat16 hb = __float2bfloat16(b);
    __nv_bfloat16 la = __float2bfloat16(a - __bfloat162float(ha));
    __nv_bfloat16 lb = __float2bfloat16(b - __bfloat162float(hb));
    __nv_bfloat162 ph; ph.x = ha; ph.y = hb;
    __nv_bfloat162 pl; pl.x = la; pl.y = lb;
    hi = *reinterpret_cast<uint32_t*>(&ph);
    lo = *reinterpret_cast<uint32_t*>(&pl);
}
__device__ __forceinline__ float gelu_exact(float x) {
    return 0.5f * x * (1.0f + erff(x * 0.70710678118654752f));
}
__device__ __forceinline__ void sts64(uint32_t addr, uint32_t a, uint32_t b) {
    asm volatile("st.shared.v2.b32 [%0], {%1, %2};" :: "r"(addr), "r"(a), "r"(b) : "memory");
}
__device__ __forceinline__ void sts128(uint32_t addr, uint4 v) {
    asm volatile("st.shared.v4.b32 [%0], {%1, %2, %3, %4};"
                 :: "r"(addr), "r"(v.x), "r"(v.y), "r"(v.z), "r"(v.w) : "memory");
}
#define LDSM4(r, addr)                                                           \
    asm volatile("ldmatrix.sync.aligned.m8n8.x4.shared.b16 {%0,%1,%2,%3}, [%4];" \
                 : "=r"((r)[0]), "=r"((r)[1]), "=r"((r)[2]), "=r"((r)[3])        \
                 : "r"(addr))
#define LDSM4T(r, addr)                                                          \
    asm volatile("ldmatrix.sync.aligned.m8n8.x4.trans.shared.b16 {%0,%1,%2,%3}, [%4];" \
                 : "=r"((r)[0]), "=r"((r)[1]), "=r"((r)[2]), "=r"((r)[3])        \
                 : "r"(addr))
#define MMA_BF16(d, a, b0, b1)                                                   \
    asm volatile("mma.sync.aligned.m16n8k16.row.col.f32.bf16.bf16.f32 "          \
                 "{%0,%1,%2,%3}, {%4,%5,%6,%7}, {%8,%9}, {%0,%1,%2,%3};"         \
                 : "+f"((d)[0]), "+f"((d)[1]), "+f"((d)[2]), "+f"((d)[3])        \
                 : "r"((a)[0]), "r"((a)[1]), "r"((a)[2]), "r"((a)[3]),           \
                   "r"(b0), "r"(b1))

// ---------------- bookkeeping (proven, unchanged) ----------------------------
__global__ void moe_init() {
    if (threadIdx.x < EE) g_counts[threadIdx.x] = 0;
}

__global__ void moe_router(const float* __restrict__ x, const float* __restrict__ gw) {
    __shared__ float sg[EE * DD];
    for (int i = threadIdx.x; i < EE * DD; i += blockDim.x) sg[i] = gw[i];
    __syncthreads();
    const int warp = threadIdx.x >> 5, lane = threadIdx.x & 31;
    const int token = blockIdx.x * 8 + warp;
    const float* xr = x + (size_t)token * DD;
    float acc[EE];
    #pragma unroll
    for (int e = 0; e < EE; e++) acc[e] = 0.f;
    for (int k = lane; k < DD; k += 32) {
        const float xv = xr[k];
        #pragma unroll
        for (int e = 0; e < EE; e++) acc[e] = fmaf(xv, sg[e * DD + k], acc[e]);
    }
    #pragma unroll
    for (int e = 0; e < EE; e++) {
        #pragma unroll
        for (int off = 16; off > 0; off >>= 1)
            acc[e] += __shfl_xor_sync(0xffffffffu, acc[e], off);
    }
    if (lane == 0) {
        int best = 0; float bv = acc[0];
        #pragma unroll
        for (int e = 1; e < EE; e++)
            if (acc[e] > bv) { bv = acc[e]; best = e; }   // first-max = jnp.argmax
        g_expert_id[token] = best;
        atomicAdd(&g_counts[best], 1);
    }
}

__global__ void moe_scan() {
    if (threadIdx.x == 0) {
        int s = 0;
        for (int e = 0; e < EE; e++) { g_offsets[e] = s; g_cursor[e] = s; s += g_counts[e]; }
    }
}

__global__ void moe_scatter() {
    const int t = blockIdx.x * blockDim.x + threadIdx.x;
    if (t >= TT) return;
    const int e = g_expert_id[t];
    g_perm[atomicAdd(&g_cursor[e], 1)] = t;
}

// ---------------- grouped GEMM: mma.sync bf16 hi/lo (3-pass fp32 emu) -------
// CTA 128M x 128N, K-stage 16, static-SMEM double buffer. Same SMEM layout and
// dataflow as the passing R5 kernel; ONLY change: 512 threads (16 warps of
// 32x32 tiles) for 4 warps/SMSP latency hiding, halved per-thread registers.
template<int KDIM, int NDIM, int PHASE>
__global__ __launch_bounds__(512) void moe_gemm_mma(
    const float* __restrict__ Araw,     // PHASE1: x [TT][DD]
    const float* __restrict__ Wraw,     // [EE][KDIM][NDIM]
    float* __restrict__ Out)
{
    // layout: A(buf,split) = (buf*2+split)*6144, row stride 48  (128 rows)
    //         B(buf,split) = 24576 + (buf*2+split)*4352, row stride 272 (16 rows)
    __shared__ __align__(128) char sm[41984];
    const int e   = blockIdx.z;
    const int cnt = g_counts[e];
    const int m0  = blockIdx.x * 128;
    if (m0 >= cnt) return;
    const int off = g_offsets[e];
    const int n0  = blockIdx.y * 128;
    const uint32_t sb = smem_u32(sm);

    const int tid = threadIdx.x, lane = tid & 31, wid = tid >> 5;
    const int warpM = wid >> 2, warpN = wid & 3;   // 4 x 4 warps, 32x32 tiles

    // ---- fixed per-thread source pointers ----
    // A PHASE1: one float4 per thread: row tid>>2 (0..127), k-chunk (tid&3)*4
    const int rowA = tid >> 2;
    const int k4   = (tid & 3) * 4;
    const float* aP1 = nullptr;
    bool aV = false;
    // A PHASE2: one 16B chunk per thread: split tid>>8, row (tid&255)>>1, half (tid&1)
    const __nv_bfloat16* aP2 = nullptr;
    if (PHASE == 1) {
        aV = (m0 + rowA) < cnt;
        const size_t tok = aV ? (size_t)g_perm[off + m0 + rowA] : 0;
        aP1 = Araw + tok * KDIM + k4;
    } else {
        const int idx = tid & 255;
        const int r   = idx >> 1;
        const int rc  = (m0 + r) < cnt ? r : 0;
        const __nv_bfloat16* src = (tid < 256) ? g_h_hi : g_h_lo;
        aP2 = src + (size_t)(off + m0 + rc) * KDIM + (idx & 1) * 8;
    }
    // B: one float4 per thread: k-row tid>>5 (0..15), n-chunk (tid&31)*4
    const int krow = tid >> 5;
    const int c4   = (tid & 31) * 4;
    const float* bP = Wraw + (size_t)e * KDIM * NDIM + n0 + c4;

    // ---- staging registers (single slot, as in R5) ----
    float4 aS;  uint4 aS2;  float4 bS;

    auto ldg_stage = [&](int s) {
        const int k0 = s * 16;
        if (PHASE == 1) {
            aS = aV ? *(const float4*)(aP1 + k0) : make_float4(0.f, 0.f, 0.f, 0.f);
        } else {
            aS2 = *(const uint4*)(aP2 + k0);
        }
        bS = *(const float4*)(bP + (size_t)(k0 + krow) * NDIM);
    };
    auto sts_stage = [&](int s) {
        const int buf = s & 1;
        const uint32_t ah = sb + (uint32_t)(buf * 2) * 6144;
        const uint32_t al = ah + 6144;
        if (PHASE == 1) {
            uint32_t h0, l0, h1, l1;
            split2(aS.x, aS.y, h0, l0);
            split2(aS.z, aS.w, h1, l1);
            const uint32_t o = (uint32_t)rowA * 48 + (uint32_t)k4 * 2;
            sts64(ah + o, h0, h1);
            sts64(al + o, l0, l1);
        } else {
            const int idx = tid & 255;
            const uint32_t o = (uint32_t)(idx >> 1) * 48 + (uint32_t)(idx & 1) * 16;
            sts128(((tid < 256) ? ah : al) + o, aS2);
        }
        const uint32_t bh = sb + 24576 + (uint32_t)(buf * 2) * 4352;
        const uint32_t bl = bh + 4352;
        {
            uint32_t h0, l0, h1, l1;
            split2(bS.x, bS.y, h0, l0);
            split2(bS.z, bS.w, h1, l1);
            const uint32_t o = (uint32_t)krow * 272 + (uint32_t)c4 * 2;
            sts64(bh + o, h0, h1);
            sts64(bl + o, l0, l1);
        }
    };

    float acc[2][4][4];
    #pragma unroll
    for (int a = 0; a < 2; ++a)
        #pragma unroll
        for (int b = 0; b < 4; ++b)
            #pragma unroll
            for (int c = 0; c < 4; ++c) acc[a][b][c] = 0.f;

    // ldmatrix per-thread offsets (same formulas, warp tile now 32x32)
    const uint32_t aFragOff =
        (uint32_t)(warpM * 32 + (lane & 15)) * 48 + (uint32_t)(lane >> 4) * 16;
    const uint32_t bFragOff =
        (uint32_t)(lane & 15) * 272 + (uint32_t)(warpN * 64) + (uint32_t)(lane >> 4) * 16;

    constexpr int NS = KDIM / 16;
    ldg_stage(0);
    sts_stage(0);
    __syncthreads();

    for (int s = 0; s < NS; ++s) {
        if (s + 1 < NS) ldg_stage(s + 1);

        const int buf = s & 1;
        const uint32_t aH = sb + (uint32_t)(buf * 2) * 6144 + aFragOff;
        const uint32_t aL = aH + 6144;
        const uint32_t bH = sb + 24576 + (uint32_t)(buf * 2) * 4352 + bFragOff;
        const uint32_t bL = bH + 4352;

        uint32_t ah[2][4], al[2][4], bh[2][4], bl[2][4];
        #pragma unroll
        for (int mf = 0; mf < 2; ++mf) {
            LDSM4(ah[mf], aH + (uint32_t)mf * 768);   // 16 rows * 48B
            LDSM4(al[mf], aL + (uint32_t)mf * 768);
        }
        #pragma unroll
        for (int nq = 0; nq < 2; ++nq) {
            LDSM4T(bh[nq], bH + (uint32_t)nq * 32);   // 16 n-cols * 2B
            LDSM4T(bl[nq], bL + (uint32_t)nq * 32);
        }
        #pragma unroll
        for (int mf = 0; mf < 2; ++mf)
            #pragma unroll
            for (int nf = 0; nf < 4; ++nf) {
                const int nq = nf >> 1, hh = nf & 1;
                MMA_BF16(acc[mf][nf], ah[mf], bh[nq][2 * hh], bh[nq][2 * hh + 1]);
                MMA_BF16(acc[mf][nf], ah[mf], bl[nq][2 * hh], bl[nq][2 * hh + 1]);
                MMA_BF16(acc[mf][nf], al[mf], bh[nq][2 * hh], bh[nq][2 * hh + 1]);
            }

        if (s + 1 < NS) {
            sts_stage(s + 1);
            __syncthreads();
        }
    }

    // ---- epilogue ----
    const int rBase = m0 + warpM * 32 + (lane >> 2);
    const int cBase = n0 + warpN * 32 + (lane & 3) * 2;
    #pragma unroll
    for (int mf = 0; mf < 2; ++mf) {
        #pragma unroll
        for (int rr = 0; rr < 2; ++rr) {
            const int gr = rBase + mf * 16 + rr * 8;
            if (gr >= cnt) continue;
            if (PHASE == 1) {
                const size_t rowoff = (size_t)(off + gr) * NDIM;
                #pragma unroll
                for (int nf = 0; nf < 4; ++nf) {
                    const float f0 = gelu_exact(acc[mf][nf][rr * 2 + 0]);
                    const float f1 = gelu_exact(acc[mf][nf][rr * 2 + 1]);
                    uint32_t h, l;
                    split2(f0, f1, h, l);
                    *reinterpret_cast<uint32_t*>(g_h_hi + rowoff + cBase + nf * 8) = h;
                    *reinterpret_cast<uint32_t*>(g_h_lo + rowoff + cBase + nf * 8) = l;
                }
            } else {
                const int tok = g_perm[off + gr];
                float* dst = Out + (size_t)tok * DD + cBase;
                #pragma unroll
                for (int nf = 0; nf < 4; ++nf)
                    *reinterpret_cast<float2*>(dst + nf * 8) =
                        make_float2(acc[mf][nf][rr * 2 + 0], acc[mf][nf][rr * 2 + 1]);
            }
        }
    }
}

// ---------------- launch ----------------------------------------------------
extern "C" void kernel_launch(void* const* d_in, const int* in_sizes, int n_in,
                              void* d_out, int out_size) {
    (void)in_sizes; (void)n_in; (void)out_size;
    const float* x  = (const float*)d_in[0];
    const float* gw = (const float*)d_in[1];
    const float* w1 = (const float*)d_in[2];   // [E][D][F]
    const float* w2 = (const float*)d_in[3];   // [E][F][D]
    float* out = (float*)d_out;

    moe_init<<<1, 32>>>();
    moe_router<<<TT / 8, 256>>>(x, gw);
    moe_scan<<<1, 1>>>();
    moe_scatter<<<TT / 256, 256>>>();

    // GEMM1: h = gelu(x_gathered @ w1[e]); K=D, N=F
    moe_gemm_mma<DD, FF, 1><<<dim3(32, FF / 128, EE), 512>>>(x, w1, nullptr);
    // GEMM2: out = h @ w2[e] scattered; K=F, N=D
    moe_gemm_mma<FF, DD, 2><<<dim3(32, DD / 128, EE), 512>>>(x, w2, out);
}

// round 9
// speedup vs baseline: 1.5289x; 1.5289x over previous
#include <cuda_runtime.h>
#include <cuda_bf16.h>
#include <cstdint>
#include <math.h>

namespace {
constexpr int TT = 4096;   // tokens (B*S)
constexpr int DD = 1024;   // model dim
constexpr int EE = 8;      // experts
constexpr int FF = 4096;   // ffn dim
}

// ---------------- device scratch (no runtime allocation allowed) -----------
__device__ int g_expert_id[TT];
__device__ int g_counts[EE];
__device__ int g_offsets[EE];
__device__ int g_cursor[EE];
__device__ int g_perm[TT];
__device__ __nv_bfloat16 g_h_hi[(size_t)TT * FF];   // 32 MB
__device__ __nv_bfloat16 g_h_lo[(size_t)TT * FF];   // 32 MB

// ---------------- helpers ---------------------------------------------------
__device__ __forceinline__ uint32_t smem_u32(const void* p) {
    uint32_t a;
    asm("{ .reg .u64 t; cvta.to.shared.u64 t, %1; cvt.u32.u64 %0, t; }" : "=r"(a) : "l"(p));
    return a;
}
// fp32 -> bf16 (hi, lo) split, packed as bf16x2 pairs
__device__ __forceinline__ void split2(float a, float b, uint32_t& hi, uint32_t& lo) {
    __nv_bfloat16 ha = __float2bfloat16(a);
    __nv_bfloat16 hb = __float2bfloat16(b);
    __nv_bfloat16 la = __float2bfloat16(a - __bfloat162float(ha));
    __nv_bfloat16 lb = __float2bfloat16(b - __bfloat162float(hb));
    __nv_bfloat162 ph; ph.x = ha; ph.y = hb;
    __nv_bfloat162 pl; pl.x = la; pl.y = lb;
    hi = *reinterpret_cast<uint32_t*>(&ph);
    lo = *reinterpret_cast<uint32_t*>(&pl);
}
__device__ __forceinline__ float gelu_exact(float x) {
    return 0.5f * x * (1.0f + erff(x * 0.70710678118654752f));
}
__device__ __forceinline__ void sts64(uint32_t addr, uint32_t a, uint32_t b) {
    asm volatile("st.shared.v2.b32 [%0], {%1, %2};" :: "r"(addr), "r"(a), "r"(b) : "memory");
}
__device__ __forceinline__ void sts128(uint32_t addr, uint4 v) {
    asm volatile("st.shared.v4.b32 [%0], {%1, %2, %3, %4};"
                 :: "r"(addr), "r"(v.x), "r"(v.y), "r"(v.z), "r"(v.w) : "memory");
}
#define LDSM4(r, addr)                                                           \
    asm volatile("ldmatrix.sync.aligned.m8n8.x4.shared.b16 {%0,%1,%2,%3}, [%4];" \
                 : "=r"((r)[0]), "=r"((r)[1]), "=r"((r)[2]), "=r"((r)[3])        \
                 : "r"(addr))
#define LDSM4T(r, addr)                                                          \
    asm volatile("ldmatrix.sync.aligned.m8n8.x4.trans.shared.b16 {%0,%1,%2,%3}, [%4];" \
                 : "=r"((r)[0]), "=r"((r)[1]), "=r"((r)[2]), "=r"((r)[3])        \
                 : "r"(addr))
#define MMA_BF16(d, a, b0, b1)                                                   \
    asm volatile("mma.sync.aligned.m16n8k16.row.col.f32.bf16.bf16.f32 "          \
                 "{%0,%1,%2,%3}, {%4,%5,%6,%7}, {%8,%9}, {%0,%1,%2,%3};"         \
                 : "+f"((d)[0]), "+f"((d)[1]), "+f"((d)[2]), "+f"((d)[3])        \
                 : "r"((a)[0]), "r"((a)[1]), "r"((a)[2]), "r"((a)[3]),           \
                   "r"(b0), "r"(b1))

// ---------------- bookkeeping (proven, unchanged) ----------------------------
__global__ void moe_init() {
    if (threadIdx.x < EE) g_counts[threadIdx.x] = 0;
}

__global__ void moe_router(const float* __restrict__ x, const float* __restrict__ gw) {
    __shared__ float sg[EE * DD];
    for (int i = threadIdx.x; i < EE * DD; i += blockDim.x) sg[i] = gw[i];
    __syncthreads();
    const int warp = threadIdx.x >> 5, lane = threadIdx.x & 31;
    const int token = blockIdx.x * 8 + warp;
    const float* xr = x + (size_t)token * DD;
    float acc[EE];
    #pragma unroll
    for (int e = 0; e < EE; e++) acc[e] = 0.f;
    for (int k = lane; k < DD; k += 32) {
        const float xv = xr[k];
        #pragma unroll
        for (int e = 0; e < EE; e++) acc[e] = fmaf(xv, sg[e * DD + k], acc[e]);
    }
    #pragma unroll
    for (int e = 0; e < EE; e++) {
        #pragma unroll
        for (int off = 16; off > 0; off >>= 1)
            acc[e] += __shfl_xor_sync(0xffffffffu, acc[e], off);
    }
    if (lane == 0) {
        int best = 0; float bv = acc[0];
        #pragma unroll
        for (int e = 1; e < EE; e++)
            if (acc[e] > bv) { bv = acc[e]; best = e; }   // first-max = jnp.argmax
        g_expert_id[token] = best;
        atomicAdd(&g_counts[best], 1);
    }
}

__global__ void moe_scan() {
    if (threadIdx.x == 0) {
        int s = 0;
        for (int e = 0; e < EE; e++) { g_offsets[e] = s; g_cursor[e] = s; s += g_counts[e]; }
    }
}

__global__ void moe_scatter() {
    const int t = blockIdx.x * blockDim.x + threadIdx.x;
    if (t >= TT) return;
    const int e = g_expert_id[t];
    g_perm[atomicAdd(&g_cursor[e], 1)] = t;
}

// dummy no-op launch: shifts GEMM1 to launch index 5 so ncu -s 5 -c 1 profiles it
__global__ void moe_nop() {}

// ---------------- grouped GEMM: mma.sync bf16 hi/lo (3-pass fp32 emu) -------
// CTA 128M x 128N tile, K-stage 16, static-SMEM double buffer (41984 B), but
// with 128 threads / 4 warps of 64x64 (R6-validated warp mapping) so that
// 2 CTAs co-reside per SM (regs ~210/thr, 2x42KB smem) and barrier stalls of
// one CTA are covered by the other. SMEM layout identical to R5:
//   A(buf,split) = (buf*2+split)*6144, row stride 48  (128 rows)
//   B(buf,split) = 24576 + (buf*2+split)*4352, row stride 272 (16 rows)
template<int KDIM, int NDIM, int PHASE>
__global__ __launch_bounds__(128) void moe_gemm_mma(
    const float* __restrict__ Araw,     // PHASE1: x [TT][DD]
    const float* __restrict__ Wraw,     // [EE][KDIM][NDIM]
    float* __restrict__ Out)
{
    __shared__ __align__(128) char sm[41984];
    const int e   = blockIdx.z;
    const int cnt = g_counts[e];
    const int m0  = blockIdx.x * 128;
    if (m0 >= cnt) return;
    const int off = g_offsets[e];
    const int n0  = blockIdx.y * 128;
    const uint32_t sb = smem_u32(sm);

    const int tid = threadIdx.x, lane = tid & 31, wid = tid >> 5;
    const int warpM = wid >> 1, warpN = wid & 1;   // 2 x 2 warps, 64x64 tiles

    // ---- fixed per-thread source pointers ----
    // A: thread == row (128 threads = 128 rows)
    const float* aP1 = nullptr;
    bool aV = false;
    const __nv_bfloat16 *aP2h = nullptr, *aP2l = nullptr;
    if (PHASE == 1) {
        aV = (m0 + tid) < cnt;
        const size_t tok = aV ? (size_t)g_perm[off + m0 + tid] : 0;
        aP1 = Araw + tok * KDIM;
    } else {
        const int rc = (m0 + tid) < cnt ? tid : 0;
        const size_t rowoff = (size_t)(off + m0 + rc) * KDIM;
        aP2h = g_h_hi + rowoff;
        aP2l = g_h_lo + rowoff;
    }
    // B: thread -> k-row tid>>3 (0..15), col chunks (tid&7)*4 + i*32
    const int krow = tid >> 3;
    const int cb   = (tid & 7) * 4;
    const float* bP = Wraw + (size_t)e * KDIM * NDIM + n0 + cb;
    const uint32_t aRowOff = (uint32_t)tid * 48;
    const uint32_t bRowOff = (uint32_t)krow * 272 + (uint32_t)cb * 2;

    // ---- staging registers ----
    float4 aS[4];  uint4 aSh[2], aSl[2];  float4 bS[4];

    auto ldg_stage = [&](int s) {
        const int k0 = s * 16;
        if (PHASE == 1) {
            #pragma unroll
            for (int j = 0; j < 4; ++j)
                aS[j] = aV ? *(const float4*)(aP1 + k0 + j * 4)
                           : make_float4(0.f, 0.f, 0.f, 0.f);
        } else {
            #pragma unroll
            for (int j = 0; j < 2; ++j) {
                aSh[j] = *(const uint4*)(aP2h + k0 + j * 8);
                aSl[j] = *(const uint4*)(aP2l + k0 + j * 8);
            }
        }
        const size_t bk = (size_t)(k0 + krow) * NDIM;
        #pragma unroll
        for (int i = 0; i < 4; ++i)
            bS[i] = *(const float4*)(bP + bk + i * 32);
    };
    auto sts_stage = [&](int s) {
        const int buf = s & 1;
        const uint32_t ah = sb + (uint32_t)(buf * 2) * 6144;
        const uint32_t al = ah + 6144;
        if (PHASE == 1) {
            #pragma unroll
            for (int j = 0; j < 4; ++j) {
                uint32_t h0, l0, h1, l1;
                split2(aS[j].x, aS[j].y, h0, l0);
                split2(aS[j].z, aS[j].w, h1, l1);
                const uint32_t o = aRowOff + (uint32_t)j * 8;
                sts64(ah + o, h0, h1);
                sts64(al + o, l0, l1);
            }
        } else {
            #pragma unroll
            for (int j = 0; j < 2; ++j) {
                const uint32_t o = aRowOff + (uint32_t)j * 16;
                sts128(ah + o, aSh[j]);
                sts128(al + o, aSl[j]);
            }
        }
        const uint32_t bh = sb + 24576 + (uint32_t)(buf * 2) * 4352;
        const uint32_t bl = bh + 4352;
        #pragma unroll
        for (int i = 0; i < 4; ++i) {
            uint32_t h0, l0, h1, l1;
            split2(bS[i].x, bS[i].y, h0, l0);
            split2(bS[i].z, bS[i].w, h1, l1);
            const uint32_t o = bRowOff + (uint32_t)i * 64;
            sts64(bh + o, h0, h1);
            sts64(bl + o, l0, l1);
        }
    };

    float acc[4][8][4];
    #pragma unroll
    for (int a = 0; a < 4; ++a)
        #pragma unroll
        for (int b = 0; b < 8; ++b)
            #pragma unroll
            for (int c = 0; c < 4; ++c) acc[a][b][c] = 0.f;

    // ldmatrix per-thread offsets (R5 formulas, warp tiles now 64x64)
    const uint32_t aFragOff =
        (uint32_t)(warpM * 64 + (lane & 15)) * 48 + (uint32_t)(lane >> 4) * 16;
    const uint32_t bFragOff =
        (uint32_t)(lane & 15) * 272 + (uint32_t)(warpN * 128) + (uint32_t)(lane >> 4) * 16;

    constexpr int NS = KDIM / 16;
    ldg_stage(0);
    sts_stage(0);
    __syncthreads();

    for (int s = 0; s < NS; ++s) {
        if (s + 1 < NS) ldg_stage(s + 1);

        const int buf = s & 1;
        const uint32_t aH = sb + (uint32_t)(buf * 2) * 6144 + aFragOff;
        const uint32_t aL = aH + 6144;
        const uint32_t bH = sb + 24576 + (uint32_t)(buf * 2) * 4352 + bFragOff;
        const uint32_t bL = bH + 4352;

        uint32_t ah[4][4], al[4][4];
        #pragma unroll
        for (int mf = 0; mf < 4; ++mf) {
            LDSM4(ah[mf], aH + (uint32_t)mf * 768);   // 16 rows * 48B
            LDSM4(al[mf], aL + (uint32_t)mf * 768);
        }
        #pragma unroll
        for (int nq = 0; nq < 4; ++nq) {
            uint32_t bh[4], bl[4];
            LDSM4T(bh, bH + (uint32_t)nq * 32);       // 16 n-cols * 2B
            LDSM4T(bl, bL + (uint32_t)nq * 32);
            #pragma unroll
            for (int mf = 0; mf < 4; ++mf)
                #pragma unroll
                for (int hh = 0; hh < 2; ++hh) {
                    float* d = acc[mf][nq * 2 + hh];
                    MMA_BF16(d, ah[mf], bh[2 * hh], bh[2 * hh + 1]);
                    MMA_BF16(d, ah[mf], bl[2 * hh], bl[2 * hh + 1]);
                    MMA_BF16(d, al[mf], bh[2 * hh], bh[2 * hh + 1]);
                }
        }

        if (s + 1 < NS) {
            sts_stage(s + 1);
            __syncthreads();
        }
    }

    // ---- epilogue (R6-validated 64x64 warp mapping) ----
    const int rBase = m0 + warpM * 64 + (lane >> 2);
    const int cBase = n0 + warpN * 64 + (lane & 3) * 2;
    #pragma unroll
    for (int mf = 0; mf < 4; ++mf) {
        #pragma unroll
        for (int rr = 0; rr < 2; ++rr) {
            const int gr = rBase + mf * 16 + rr * 8;
            if (gr >= cnt) continue;
            if (PHASE == 1) {
                const size_t rowoff = (size_t)(off + gr) * NDIM;
                #pragma unroll
                for (int nf = 0; nf < 8; ++nf) {
                    const float f0 = gelu_exact(acc[mf][nf][rr * 2 + 0]);
                    const float f1 = gelu_exact(acc[mf][nf][rr * 2 + 1]);
                    uint32_t h, l;
                    split2(f0, f1, h, l);
                    *reinterpret_cast<uint32_t*>(g_h_hi + rowoff + cBase + nf * 8) = h;
                    *reinterpret_cast<uint32_t*>(g_h_lo + rowoff + cBase + nf * 8) = l;
                }
            } else {
                const int tok = g_perm[off + gr];
                float* dst = Out + (size_t)tok * DD + cBase;
                #pragma unroll
                for (int nf = 0; nf < 8; ++nf)
                    *reinterpret_cast<float2*>(dst + nf * 8) =
                        make_float2(acc[mf][nf][rr * 2 + 0], acc[mf][nf][rr * 2 + 1]);
            }
        }
    }
}

// ---------------- launch ----------------------------------------------------
extern "C" void kernel_launch(void* const* d_in, const int* in_sizes, int n_in,
                              void* d_out, int out_size) {
    (void)in_sizes; (void)n_in; (void)out_size;
    const float* x  = (const float*)d_in[0];
    const float* gw = (const float*)d_in[1];
    const float* w1 = (const float*)d_in[2];   // [E][D][F]
    const float* w2 = (const float*)d_in[3];   // [E][F][D]
    float* out = (float*)d_out;

    moe_init<<<1, 32>>>();                      // launch 0
    moe_router<<<TT / 8, 256>>>(x, gw);         // launch 1
    moe_scan<<<1, 1>>>();                       // launch 2
    moe_scatter<<<TT / 256, 256>>>();           // launch 3
    moe_nop<<<1, 32>>>();                       // launch 4 (aligns ncu -s 5 on GEMM1)

    // GEMM1: h = gelu(x_gathered @ w1[e]); K=D, N=F   -> launch 5
    moe_gemm_mma<DD, FF, 1><<<dim3(32, FF / 128, EE), 128>>>(x, w1, nullptr);
    // GEMM2: out = h @ w2[e] scattered; K=F, N=D      -> launch 6
    moe_gemm_mma<FF, DD, 2><<<dim3(32, DD / 128, EE), 128>>>(x, w2, out);
}

// round 10
// speedup vs baseline: 1.6794x; 1.0984x over previous
#include <cuda_runtime.h>
#include <cuda_bf16.h>
#include <cstdint>
#include <math.h>

namespace {
constexpr int TT = 4096;   // tokens (B*S)
constexpr int DD = 1024;   // model dim
constexpr int EE = 8;      // experts
constexpr int FF = 4096;   // ffn dim
}

// ---------------- device scratch (no runtime allocation allowed) -----------
__device__ int g_expert_id[TT];
__device__ int g_counts[EE];
__device__ int g_offsets[EE];
__device__ int g_cursor[EE];
__device__ int g_perm[TT];
__device__ __nv_bfloat16 g_h_hi[(size_t)TT * FF];   // 32 MB
__device__ __nv_bfloat16 g_h_lo[(size_t)TT * FF];   // 32 MB

// ---------------- helpers ---------------------------------------------------
__device__ __forceinline__ uint32_t smem_u32(const void* p) {
    uint32_t a;
    asm("{ .reg .u64 t; cvta.to.shared.u64 t, %1; cvt.u32.u64 %0, t; }" : "=r"(a) : "l"(p));
    return a;
}
// fp32 -> bf16 (hi, lo) split, packed as bf16x2 pairs
__device__ __forceinline__ void split2(float a, float b, uint32_t& hi, uint32_t& lo) {
    __nv_bfloat16 ha = __float2bfloat16(a);
    __nv_bfloat16 hb = __float2bfloat16(b);
    __nv_bfloat16 la = __float2bfloat16(a - __bfloat162float(ha));
    __nv_bfloat16 lb = __float2bfloat16(b - __bfloat162float(hb));
    __nv_bfloat162 ph; ph.x = ha; ph.y = hb;
    __nv_bfloat162 pl; pl.x = la; pl.y = lb;
    hi = *reinterpret_cast<uint32_t*>(&ph);
    lo = *reinterpret_cast<uint32_t*>(&pl);
}
__device__ __forceinline__ float gelu_exact(float x) {
    return 0.5f * x * (1.0f + erff(x * 0.70710678118654752f));
}
__device__ __forceinline__ void sts64(uint32_t addr, uint32_t a, uint32_t b) {
    asm volatile("st.shared.v2.b32 [%0], {%1, %2};" :: "r"(addr), "r"(a), "r"(b) : "memory");
}
__device__ __forceinline__ void sts128(uint32_t addr, uint4 v) {
    asm volatile("st.shared.v4.b32 [%0], {%1, %2, %3, %4};"
                 :: "r"(addr), "r"(v.x), "r"(v.y), "r"(v.z), "r"(v.w) : "memory");
}
#define LDSM4(r, addr)                                                           \
    asm volatile("ldmatrix.sync.aligned.m8n8.x4.shared.b16 {%0,%1,%2,%3}, [%4];" \
                 : "=r"((r)[0]), "=r"((r)[1]), "=r"((r)[2]), "=r"((r)[3])        \
                 : "r"(addr))
#define LDSM4T(r, addr)                                                          \
    asm volatile("ldmatrix.sync.aligned.m8n8.x4.trans.shared.b16 {%0,%1,%2,%3}, [%4];" \
                 : "=r"((r)[0]), "=r"((r)[1]), "=r"((r)[2]), "=r"((r)[3])        \
                 : "r"(addr))
#define MMA_BF16(d, a, b0, b1)                                                   \
    asm volatile("mma.sync.aligned.m16n8k16.row.col.f32.bf16.bf16.f32 "          \
                 "{%0,%1,%2,%3}, {%4,%5,%6,%7}, {%8,%9}, {%0,%1,%2,%3};"         \
                 : "+f"((d)[0]), "+f"((d)[1]), "+f"((d)[2]), "+f"((d)[3])        \
                 : "r"((a)[0]), "r"((a)[1]), "r"((a)[2]), "r"((a)[3]),           \
                   "r"(b0), "r"(b1))

// ---------------- bookkeeping ------------------------------------------------
__global__ void moe_init() {
    if (threadIdx.x < EE) g_counts[threadIdx.x] = 0;
}

__global__ void moe_router(const float* __restrict__ x, const float* __restrict__ gw) {
    __shared__ float sg[EE * DD];
    for (int i = threadIdx.x; i < EE * DD; i += blockDim.x) sg[i] = gw[i];
    __syncthreads();
    const int warp = threadIdx.x >> 5, lane = threadIdx.x & 31;
    const int token = blockIdx.x * 8 + warp;
    const float* xr = x + (size_t)token * DD;
    float acc[EE];
    #pragma unroll
    for (int e = 0; e < EE; e++) acc[e] = 0.f;
    for (int k = lane; k < DD; k += 32) {
        const float xv = xr[k];
        #pragma unroll
        for (int e = 0; e < EE; e++) acc[e] = fmaf(xv, sg[e * DD + k], acc[e]);
    }
    #pragma unroll
    for (int e = 0; e < EE; e++) {
        #pragma unroll
        for (int off = 16; off > 0; off >>= 1)
            acc[e] += __shfl_xor_sync(0xffffffffu, acc[e], off);
    }
    if (lane == 0) {
        int best = 0; float bv = acc[0];
        #pragma unroll
        for (int e = 1; e < EE; e++)
            if (acc[e] > bv) { bv = acc[e]; best = e; }   // first-max = jnp.argmax
        g_expert_id[token] = best;
        atomicAdd(&g_counts[best], 1);
    }
}

// fused scan + scatter (single block) so GEMM1 is our 4th launch -> ncu -s 5
__global__ void moe_scan_scatter() {
    if (threadIdx.x == 0) {
        int s = 0;
        for (int e = 0; e < EE; e++) { g_offsets[e] = s; g_cursor[e] = s; s += g_counts[e]; }
    }
    __syncthreads();
    for (int t = threadIdx.x; t < TT; t += blockDim.x) {
        const int e = g_expert_id[t];
        g_perm[atomicAdd(&g_cursor[e], 1)] = t;
    }
}

// ---------------- grouped GEMM: mma.sync bf16 hi/lo (3-pass fp32 emu) -------
// Identical to the 643us R5 kernel EXCEPT the MMA issue order: three separate
// passes (all hi*hi, then all hi*lo, then all lo*hi) so consecutive MMAs to
// the same accumulator are ~16 instructions apart instead of back-to-back.
// Per-accumulator operation order is unchanged -> bitwise-identical results.
template<int KDIM, int NDIM, int PHASE>
__global__ __launch_bounds__(256) void moe_gemm_mma(
    const float* __restrict__ Araw,     // PHASE1: x [TT][DD]
    const float* __restrict__ Wraw,     // [EE][KDIM][NDIM]
    float* __restrict__ Out)
{
    // layout: A(buf,split) = (buf*2+split)*6144, row stride 48  (128 rows)
    //         B(buf,split) = 24576 + (buf*2+split)*4352, row stride 272 (16 rows)
    __shared__ __align__(128) char sm[41984];
    const int e   = blockIdx.z;
    const int cnt = g_counts[e];
    const int m0  = blockIdx.x * 128;
    if (m0 >= cnt) return;
    const int off = g_offsets[e];
    const int n0  = blockIdx.y * 128;
    const uint32_t sb = smem_u32(sm);

    const int tid = threadIdx.x, lane = tid & 31, wid = tid >> 5;
    const int warpM = wid >> 2, warpN = wid & 3;

    // ---- fixed per-thread source pointers ----
    const int rowA0 = tid >> 2;
    const int k4    = (tid & 3) * 4;
    const float* aP1[2];
    bool aV[2];
    const __nv_bfloat16 *aP2h = nullptr, *aP2l = nullptr;
    if (PHASE == 1) {
        #pragma unroll
        for (int i = 0; i < 2; ++i) {
            const int r = rowA0 + i * 64;
            aV[i] = (m0 + r) < cnt;
            const size_t tok = aV[i] ? (size_t)g_perm[off + m0 + r] : 0;
            aP1[i] = Araw + tok * KDIM + k4;
        }
    } else {
        const int r  = tid >> 1;
        const int rc = (m0 + r) < cnt ? r : 0;
        const size_t rowoff = (size_t)(off + m0 + rc) * KDIM + (tid & 1) * 8;
        aP2h = g_h_hi + rowoff;
        aP2l = g_h_lo + rowoff;
    }
    const int krow = tid >> 5;
    const int c4   = (tid & 31) * 4;
    const float* bP = Wraw + (size_t)e * KDIM * NDIM + n0 + c4;

    // ---- staging registers ----
    float4 aS[2];  uint4 aSh, aSl;  float4 bS[2];

    auto ldg_stage = [&](int s) {
        const int k0 = s * 16;
        if (PHASE == 1) {
            #pragma unroll
            for (int i = 0; i < 2; ++i)
                aS[i] = aV[i] ? *(const float4*)(aP1[i] + k0)
                              : make_float4(0.f, 0.f, 0.f, 0.f);
        } else {
            aSh = *(const uint4*)(aP2h + k0);
            aSl = *(const uint4*)(aP2l + k0);
        }
        #pragma unroll
        for (int i = 0; i < 2; ++i)
            bS[i] = *(const float4*)(bP + (size_t)(k0 + krow + i * 8) * NDIM);
    };
    auto sts_stage = [&](int s) {
        const int buf = s & 1;
        const uint32_t ah = sb + (uint32_t)(buf * 2) * 6144;
        const uint32_t al = ah + 6144;
        if (PHASE == 1) {
            #pragma unroll
            for (int i = 0; i < 2; ++i) {
                uint32_t h0, l0, h1, l1;
                split2(aS[i].x, aS[i].y, h0, l0);
                split2(aS[i].z, aS[i].w, h1, l1);
                const uint32_t o = (uint32_t)(rowA0 + i * 64) * 48 + (uint32_t)k4 * 2;
                sts64(ah + o, h0, h1);
                sts64(al + o, l0, l1);
            }
        } else {
            const uint32_t o = (uint32_t)(tid >> 1) * 48 + (uint32_t)(tid & 1) * 16;
            sts128(ah + o, aSh);
            sts128(al + o, aSl);
        }
        const uint32_t bh = sb + 24576 + (uint32_t)(buf * 2) * 4352;
        const uint32_t bl = bh + 4352;
        #pragma unroll
        for (int i = 0; i < 2; ++i) {
            uint32_t h0, l0, h1, l1;
            split2(bS[i].x, bS[i].y, h0, l0);
            split2(bS[i].z, bS[i].w, h1, l1);
            const uint32_t o = (uint32_t)(krow + i * 8) * 272 + (uint32_t)c4 * 2;
            sts64(bh + o, h0, h1);
            sts64(bl + o, l0, l1);
        }
    };

    float acc[4][4][4];
    #pragma unroll
    for (int a = 0; a < 4; ++a)
        #pragma unroll
        for (int b = 0; b < 4; ++b)
            #pragma unroll
            for (int c = 0; c < 4; ++c) acc[a][b][c] = 0.f;

    // ldmatrix per-thread offsets
    const uint32_t aFragOff =
        (uint32_t)(warpM * 64 + (lane & 15)) * 48 + (uint32_t)(lane >> 4) * 16;
    const uint32_t bFragOff =
        (uint32_t)(lane & 15) * 272 + (uint32_t)(warpN * 64) + (uint32_t)(lane >> 4) * 16;

    constexpr int NS = KDIM / 16;
    ldg_stage(0);
    sts_stage(0);
    __syncthreads();

    for (int s = 0; s < NS; ++s) {
        if (s + 1 < NS) ldg_stage(s + 1);

        const int buf = s & 1;
        const uint32_t aH = sb + (uint32_t)(buf * 2) * 6144 + aFragOff;
        const uint32_t aL = aH + 6144;
        const uint32_t bH = sb + 24576 + (uint32_t)(buf * 2) * 4352 + bFragOff;
        const uint32_t bL = bH + 4352;

        uint32_t ah[4][4], al[4][4], bh[2][4], bl[2][4];
        #pragma unroll
        for (int mf = 0; mf < 4; ++mf) {
            LDSM4(ah[mf], aH + (uint32_t)mf * 768);   // 16 rows * 48B
            LDSM4(al[mf], aL + (uint32_t)mf * 768);
        }
        #pragma unroll
        for (int nq = 0; nq < 2; ++nq) {
            LDSM4T(bh[nq], bH + (uint32_t)nq * 32);   // 16 n-cols * 2B
            LDSM4T(bl[nq], bL + (uint32_t)nq * 32);
        }
        // pass 1: all hi*hi (16 independent accumulators)
        #pragma unroll
        for (int mf = 0; mf < 4; ++mf)
            #pragma unroll
            for (int nf = 0; nf < 4; ++nf) {
                const int nq = nf >> 1, hh = nf & 1;
                MMA_BF16(acc[mf][nf], ah[mf], bh[nq][2 * hh], bh[nq][2 * hh + 1]);
            }
        // pass 2: all hi*lo
        #pragma unroll
        for (int mf = 0; mf < 4; ++mf)
            #pragma unroll
            for (int nf = 0; nf < 4; ++nf) {
                const int nq = nf >> 1, hh = nf & 1;
                MMA_BF16(acc[mf][nf], ah[mf], bl[nq][2 * hh], bl[nq][2 * hh + 1]);
            }
        // pass 3: all lo*hi
        #pragma unroll
        for (int mf = 0; mf < 4; ++mf)
            #pragma unroll
            for (int nf = 0; nf < 4; ++nf) {
                const int nq = nf >> 1, hh = nf & 1;
                MMA_BF16(acc[mf][nf], al[mf], bh[nq][2 * hh], bh[nq][2 * hh + 1]);
            }

        if (s + 1 < NS) {
            sts_stage(s + 1);
            __syncthreads();
        }
    }

    // ---- epilogue ----
    const int rBase = m0 + warpM * 64 + (lane >> 2);
    const int cBase = n0 + warpN * 32 + (lane & 3) * 2;
    #pragma unroll
    for (int mf = 0; mf < 4; ++mf) {
        #pragma unroll
        for (int rr = 0; rr < 2; ++rr) {
            const int gr = rBase + mf * 16 + rr * 8;
            if (gr >= cnt) continue;
            if (PHASE == 1) {
                const size_t rowoff = (size_t)(off + gr) * NDIM;
                #pragma unroll
                for (int nf = 0; nf < 4; ++nf) {
                    const float f0 = gelu_exact(acc[mf][nf][rr * 2 + 0]);
                    const float f1 = gelu_exact(acc[mf][nf][rr * 2 + 1]);
                    uint32_t h, l;
                    split2(f0, f1, h, l);
                    *reinterpret_cast<uint32_t*>(g_h_hi + rowoff + cBase + nf * 8) = h;
                    *reinterpret_cast<uint32_t*>(g_h_lo + rowoff + cBase + nf * 8) = l;
                }
            } else {
                const int tok = g_perm[off + gr];
                float* dst = Out + (size_t)tok * DD + cBase;
                #pragma unroll
                for (int nf = 0; nf < 4; ++nf)
                    *reinterpret_cast<float2*>(dst + nf * 8) =
                        make_float2(acc[mf][nf][rr * 2 + 0], acc[mf][nf][rr * 2 + 1]);
            }
        }
    }
}

// ---------------- launch ----------------------------------------------------
extern "C" void kernel_launch(void* const* d_in, const int* in_sizes, int n_in,
                              void* d_out, int out_size) {
    (void)in_sizes; (void)n_in; (void)out_size;
    const float* x  = (const float*)d_in[0];
    const float* gw = (const float*)d_in[1];
    const float* w1 = (const float*)d_in[2];   // [E][D][F]
    const float* w2 = (const float*)d_in[3];   // [E][F][D]
    float* out = (float*)d_out;

    moe_init<<<1, 32>>>();                      // local 0
    moe_router<<<TT / 8, 256>>>(x, gw);         // local 1
    moe_scan_scatter<<<1, 256>>>();             // local 2
    // GEMM1: h = gelu(x_gathered @ w1[e]); K=D, N=F    local 3 (= ncu target)
    moe_gemm_mma<DD, FF, 1><<<dim3(32, FF / 128, EE), 256>>>(x, w1, nullptr);
    // GEMM2: out = h @ w2[e] scattered; K=F, N=D       local 4
    moe_gemm_mma<FF, DD, 2><<<dim3(32, DD / 128, EE), 256>>>(x, w2, out);
}